// round 1
// baseline (speedup 1.0000x reference)
#include <cuda_runtime.h>

// Problem constants (from reference)
#define B_SAMPLES  4096
#define D_DIM      768
#define N_CLASSES  1000
#define MAX_STAGES 4
#define MAX_P      8
#define SHARED_P   16

#define D_VEC (D_DIM / 4)   // 192 float4 per row

// Scratch for precomputed shared-stage means: [MAX_STAGES][D]
__device__ float g_shared_mean[MAX_STAGES * D_DIM];

// Kernel A: shared_mean[st][d] = mean over SHARED_P of shared_protos[st][p][d]
__global__ void shared_mean_kernel(const float* __restrict__ shared_protos) {
    int st = blockIdx.x;            // 0..3
    int v  = threadIdx.x;           // 0..191 (float4 lane)
    const float4* src = reinterpret_cast<const float4*>(
        shared_protos + (size_t)st * SHARED_P * D_DIM);
    float4 acc = make_float4(0.f, 0.f, 0.f, 0.f);
#pragma unroll
    for (int p = 0; p < SHARED_P; ++p) {
        float4 x = src[p * D_VEC + v];
        acc.x += x.x; acc.y += x.y; acc.z += x.z; acc.w += x.w;
    }
    const float inv = 1.0f / (float)SHARED_P;
    acc.x *= inv; acc.y *= inv; acc.z *= inv; acc.w *= inv;
    reinterpret_cast<float4*>(g_shared_mean)[st * D_VEC + v] = acc;
}

// Kernel B: one block per sample; 192 threads each own one float4 lane.
__global__ __launch_bounds__(D_VEC)
void proto_pool_kernel(const float* __restrict__ features,
                       const float* __restrict__ class_protos,
                       const int*   __restrict__ class_ids,
                       const int*   __restrict__ stages,
                       const int*   __restrict__ proto_counts,
                       float* __restrict__ out) {
    int b = blockIdx.x;
    int v = threadIdx.x;                       // 0..191

    // Uniform per-block scalars (broadcast loads)
    int cid = class_ids[b];
    int st  = stages[b];
    int cnt = proto_counts[cid * MAX_STAGES + st];

    const float4* protos = reinterpret_cast<const float4*>(
        class_protos +
        ((size_t)cid * MAX_STAGES + st) * (size_t)MAX_P * D_DIM);

    float4 sum = make_float4(0.f, 0.f, 0.f, 0.f);
    // Up to 8 independent coalesced float4 loads (MLP-friendly)
#pragma unroll
    for (int p = 0; p < MAX_P; ++p) {
        if (p < cnt) {
            float4 x = protos[p * D_VEC + v];
            sum.x += x.x; sum.y += x.y; sum.z += x.z; sum.w += x.w;
        }
    }
    float inv = 1.0f / (float)max(cnt, 1);

    float4 sh = reinterpret_cast<const float4*>(g_shared_mean)[st * D_VEC + v];
    float4 f  = reinterpret_cast<const float4*>(features)[(size_t)b * D_VEC + v];

    float4 r;
    r.x = f.x + 0.5f * (sum.x * inv + sh.x);
    r.y = f.y + 0.5f * (sum.y * inv + sh.y);
    r.z = f.z + 0.5f * (sum.z * inv + sh.z);
    r.w = f.w + 0.5f * (sum.w * inv + sh.w);
    reinterpret_cast<float4*>(out)[(size_t)b * D_VEC + v] = r;
}

extern "C" void kernel_launch(void* const* d_in, const int* in_sizes, int n_in,
                              void* d_out, int out_size) {
    const float* features      = (const float*)d_in[0];
    const float* class_protos  = (const float*)d_in[1];
    const float* shared_protos = (const float*)d_in[2];
    const int*   class_ids     = (const int*)d_in[3];
    const int*   stages        = (const int*)d_in[4];
    const int*   proto_counts  = (const int*)d_in[5];
    float* out = (float*)d_out;

    shared_mean_kernel<<<MAX_STAGES, D_VEC>>>(shared_protos);
    proto_pool_kernel<<<B_SAMPLES, D_VEC>>>(features, class_protos,
                                            class_ids, stages, proto_counts, out);
}